// round 12
// baseline (speedup 1.0000x reference)
#include <cuda_runtime.h>
#include <cstdint>

#define H   32
#define TPB 128

typedef unsigned long long u64;

// ---------- packed f32x2 helpers ----------
__device__ __forceinline__ u64 pack2(float lo, float hi) {
    u64 r; asm("mov.b64 %0, {%1, %2};" : "=l"(r) : "f"(lo), "f"(hi)); return r;
}
__device__ __forceinline__ void unpack2(u64 v, float& lo, float& hi) {
    asm("mov.b64 {%0, %1}, %2;" : "=f"(lo), "=f"(hi) : "l"(v));
}
__device__ __forceinline__ u64 ffma2(u64 a, u64 b, u64 c) {
    u64 d; asm("fma.rn.f32x2 %0, %1, %2, %3;" : "=l"(d) : "l"(a), "l"(b), "l"(c)); return d;
}
__device__ __forceinline__ float tanh_mufu(float x) {
    float r; asm("tanh.approx.f32 %0, %1;" : "=f"(r) : "f"(x)); return r;
}
// tanh on a packed pair via MUFU.TANH. Abs err ~4.9e-4 per scalar.
__device__ __forceinline__ u64 tanh2(u64 v) {
    float lo, hi; unpack2(v, lo, hi);
    return pack2(tanh_mufu(lo), tanh_mufu(hi));
}

__device__ __forceinline__ u64 pairAB(float a, float b) {
    return ((u64)__float_as_uint(b) << 32) | (u64)__float_as_uint(a);
}

// Lane packing: lo half = d-network, hi half = o-network.
// Each thread processes THREE rows so every 16B weight load feeds 6 FFMA2.
__global__ void __launch_bounds__(TPB)
damping_kernel(const float* __restrict__ x,
               const float* __restrict__ wd1, const float* __restrict__ wd2,
               const float* __restrict__ wd3, const float* __restrict__ wo1,
               const float* __restrict__ wo2, const float* __restrict__ wo3,
               const float* __restrict__ bd1, const float* __restrict__ bd2,
               const float* __restrict__ bd3, const float* __restrict__ bo1,
               const float* __restrict__ bo2, const float* __restrict__ bo3,
               float* __restrict__ out, int nRows)
{
    __shared__ u64 s_w2[H * H];          // {wd2[j][k], wo2[j][k]}
    __shared__ u64 s_w1[2 * H];          // {wd1[i][k], wo1[i][k]}
    __shared__ u64 s_b1[H], s_b2[H];     // {bd*, bo*}
    __shared__ u64 s_w3a[H];             // {wd3[j][0], wo3[j][0]}
    __shared__ u64 s_w3b[H];             // {wd3[j][1], 0}
    __shared__ u64 s_p0, s_q0;           // {bd3[0], bo3[0]}, {bd3[1], 0}

    for (int i = threadIdx.x; i < H * H; i += TPB)
        s_w2[i] = pairAB(wd2[i], wo2[i]);
    for (int i = threadIdx.x; i < 2 * H; i += TPB)
        s_w1[i] = pairAB(wd1[i], wo1[i]);
    for (int i = threadIdx.x; i < H; i += TPB) {
        s_b1[i]  = pairAB(bd1[i], bo1[i]);
        s_b2[i]  = pairAB(bd2[i], bo2[i]);
        s_w3a[i] = pairAB(wd3[2 * i], wo3[i]);
        s_w3b[i] = pairAB(wd3[2 * i + 1], 0.0f);
    }
    if (threadIdx.x == 0) {
        s_p0 = pairAB(bd3[0], bo3[0]);
        s_q0 = pairAB(bd3[1], 0.0f);
    }
    __syncthreads();

    int base = 3 * (blockIdx.x * TPB + threadIdx.x);   // rows base, base+1, base+2
    if (base >= nRows) return;
    bool r1ok = (base + 1) < nRows;
    bool r2ok = (base + 2) < nRows;

    float2 xa = *reinterpret_cast<const float2*>(x + 2 * (size_t)base);
    float2 xb = r1ok ? *reinterpret_cast<const float2*>(x + 2 * (size_t)base + 2)
                     : make_float2(0.f, 0.f);
    float2 xc = r2ok ? *reinterpret_cast<const float2*>(x + 2 * (size_t)base + 4)
                     : make_float2(0.f, 0.f);

    u64 X0a = pairAB(xa.x, xa.x), X1a = pairAB(xa.y, xa.y);
    u64 X0b = pairAB(xb.x, xb.x), X1b = pairAB(xb.y, xb.y);
    u64 X0c = pairAB(xc.x, xc.x), X1c = pairAB(xc.y, xc.y);

    // ---- layer 1 (3 rows, both nets packed per lane)
    u64 ha[H], hb[H], hc[H];
    #pragma unroll
    for (int k = 0; k < H; k++) {
        u64 w0 = s_w1[k], w1 = s_w1[H + k], b = s_b1[k];
        ha[k] = tanh2(ffma2(X1a, w1, ffma2(X0a, w0, b)));
        hb[k] = tanh2(ffma2(X1b, w1, ffma2(X0b, w0, b)));
        hc[k] = tanh2(ffma2(X1c, w1, ffma2(X0c, w0, b)));
    }

    // ---- layer 2 + 3 fused; kb width 2, 6 accumulator chains (2 k x 3 rows)
    u64 Pa = s_p0, Qa = s_q0, Pb = Pa, Qb = Qa, Pc = Pa, Qc = Qa;
    #pragma unroll
    for (int kb = 0; kb < H; kb += 2) {
        u64 bb0 = s_b2[kb], bb1 = s_b2[kb + 1];
        u64 a0 = bb0, a1 = bb1;
        u64 b0 = bb0, b1 = bb1;
        u64 c0 = bb0, c1 = bb1;
        #pragma unroll
        for (int j = 0; j < H; j++) {
            ulonglong2 w = *reinterpret_cast<const ulonglong2*>(s_w2 + j * H + kb);
            u64 hja = ha[j], hjb = hb[j], hjc = hc[j];
            a0 = ffma2(hja, w.x, a0);
            b0 = ffma2(hjb, w.x, b0);
            c0 = ffma2(hjc, w.x, c0);
            a1 = ffma2(hja, w.y, a1);
            b1 = ffma2(hjb, w.y, b1);
            c1 = ffma2(hjc, w.y, c1);
        }
        a0 = tanh2(a0); a1 = tanh2(a1);
        b0 = tanh2(b0); b1 = tanh2(b1);
        c0 = tanh2(c0); c1 = tanh2(c1);
        u64 w3a0 = s_w3a[kb],     w3b0 = s_w3b[kb];
        u64 w3a1 = s_w3a[kb + 1], w3b1 = s_w3b[kb + 1];
        Pa = ffma2(a0, w3a0, Pa);  Qa = ffma2(a0, w3b0, Qa);
        Pb = ffma2(b0, w3a0, Pb);  Qb = ffma2(b0, w3b0, Qb);
        Pc = ffma2(c0, w3a0, Pc);  Qc = ffma2(c0, w3b0, Qc);
        Pa = ffma2(a1, w3a1, Pa);  Qa = ffma2(a1, w3b1, Qa);
        Pb = ffma2(b1, w3a1, Pb);  Qb = ffma2(b1, w3b1, Qb);
        Pc = ffma2(c1, w3a1, Pc);  Qc = ffma2(c1, w3b1, Qc);
    }

    // ---- epilogue
    float d30, o3v, d31, junk;

    unpack2(Pa, d30, o3v); unpack2(Qa, d31, junk);
    {
        float aa = (fmaxf(d30, 0.f) + 0.001f) * xa.x;
        float bb = (fmaxf(d31, 0.f) + 0.001f) * xa.y;
        float cc = o3v;
        float2 ov;
        ov.x = aa * aa * xa.x + aa * cc * xa.y;
        ov.y = aa * cc * xa.x + (cc * cc + bb * bb) * xa.y;
        *reinterpret_cast<float2*>(out + 2 * (size_t)base) = ov;
    }
    if (r1ok) {
        unpack2(Pb, d30, o3v); unpack2(Qb, d31, junk);
        float aa = (fmaxf(d30, 0.f) + 0.001f) * xb.x;
        float bb = (fmaxf(d31, 0.f) + 0.001f) * xb.y;
        float cc = o3v;
        float2 ov;
        ov.x = aa * aa * xb.x + aa * cc * xb.y;
        ov.y = aa * cc * xb.x + (cc * cc + bb * bb) * xb.y;
        *reinterpret_cast<float2*>(out + 2 * (size_t)base + 2) = ov;
    }
    if (r2ok) {
        unpack2(Pc, d30, o3v); unpack2(Qc, d31, junk);
        float aa = (fmaxf(d30, 0.f) + 0.001f) * xc.x;
        float bb = (fmaxf(d31, 0.f) + 0.001f) * xc.y;
        float cc = o3v;
        float2 ov;
        ov.x = aa * aa * xc.x + aa * cc * xc.y;
        ov.y = aa * cc * xc.x + (cc * cc + bb * bb) * xc.y;
        *reinterpret_cast<float2*>(out + 2 * (size_t)base + 4) = ov;
    }
}

extern "C" void kernel_launch(void* const* d_in, const int* in_sizes, int n_in,
                              void* d_out, int out_size)
{
    const float* x   = (const float*)d_in[0];
    const float* wd1 = (const float*)d_in[1];
    const float* wd2 = (const float*)d_in[2];
    const float* wd3 = (const float*)d_in[3];
    const float* wo1 = (const float*)d_in[4];
    const float* wo2 = (const float*)d_in[5];
    const float* wo3 = (const float*)d_in[6];
    const float* bd1 = (const float*)d_in[7];
    const float* bd2 = (const float*)d_in[8];
    const float* bd3 = (const float*)d_in[9];
    const float* bo1 = (const float*)d_in[10];
    const float* bo2 = (const float*)d_in[11];
    const float* bo3 = (const float*)d_in[12];
    float* out = (float*)d_out;

    int nRows    = in_sizes[0] / 2;           // x is (B, 2)
    int nTriples = (nRows + 2) / 3;           // 3 rows per thread
    int blocks   = (nTriples + TPB - 1) / TPB;

    damping_kernel<<<blocks, TPB>>>(x, wd1, wd2, wd3, wo1, wo2, wo3,
                                    bd1, bd2, bd3, bo1, bo2, bo3,
                                    out, nRows);
}